// round 3
// baseline (speedup 1.0000x reference)
#include <cuda_runtime.h>
#include <math.h>

#define BB 2
#define TT 2048
#define CC 1024
#define HH 16
#define DD 64
#define MM (BB*TT)          // 4096
#define NOUT (BB*TT*CC)     // 4194304

// Scratch (allocation-free rule: __device__ globals)
__device__ float g_Q[BB*HH*TT*DD];
__device__ float g_K[BB*HH*TT*DD];
__device__ float g_V[BB*HH*TT*DD];
__device__ float g_AO[BB*TT*CC];

// ---------------------------------------------------------------------------
// QKV projection: Out[(b,h,t,d)] = sum_k x[(b,t),k] * W[k, h*D+d]
// blockIdx.z selects {Wq,Wk,Wv}. Optionally duplicates K/V into d_out.
// Tiling: BM=128, BN=64, BK=32, 256 threads, 8x4 per-thread tile.
// ---------------------------------------------------------------------------
__global__ __launch_bounds__(256) void gemm_qkv_kernel(
    const float* __restrict__ x, const float* __restrict__ Wq,
    const float* __restrict__ Wk, const float* __restrict__ Wv,
    float* __restrict__ kout, float* __restrict__ vout)
{
    constexpr int BM = 128, BN = 64, BK = 32;
    __shared__ float As[BK][BM + 4];   // transposed A tile
    __shared__ float Bs[BK][BN + 4];

    const float* W;
    float* Out;
    float* dup;
    if (blockIdx.z == 0)      { W = Wq; Out = g_Q; dup = nullptr; }
    else if (blockIdx.z == 1) { W = Wk; Out = g_K; dup = kout;    }
    else                      { W = Wv; Out = g_V; dup = vout;    }

    const int m0 = blockIdx.x * BM;
    const int n0 = blockIdx.y * BN;
    const int tid = threadIdx.x;
    const int tx = tid & 15;        // 0..15 -> 4 cols each
    const int ty = tid >> 4;        // 0..15 -> 8 rows each

    float acc[8][4];
    #pragma unroll
    for (int i = 0; i < 8; i++)
        #pragma unroll
        for (int j = 0; j < 4; j++) acc[i][j] = 0.0f;

    for (int k0 = 0; k0 < CC; k0 += BK) {
        // Load A tile 128x32 (4 float4 per thread), store transposed
        #pragma unroll
        for (int i = 0; i < 4; i++) {
            int idx = tid + i * 256;            // 0..1023
            int r = idx >> 3, kq = idx & 7;
            float4 a4 = *(const float4*)&x[(size_t)(m0 + r) * CC + k0 + kq * 4];
            int k4 = kq * 4;
            As[k4 + 0][r] = a4.x; As[k4 + 1][r] = a4.y;
            As[k4 + 2][r] = a4.z; As[k4 + 3][r] = a4.w;
        }
        // Load B tile 32x64 (2 float4 per thread)
        #pragma unroll
        for (int i = 0; i < 2; i++) {
            int idx = tid + i * 256;            // 0..511
            int kk = idx >> 4, cq = idx & 15;
            *(float4*)&Bs[kk][cq * 4] =
                *(const float4*)&W[(size_t)(k0 + kk) * CC + n0 + cq * 4];
        }
        __syncthreads();

        #pragma unroll 8
        for (int kk = 0; kk < BK; kk++) {
            float4 a0 = *(const float4*)&As[kk][ty * 8];
            float4 a1 = *(const float4*)&As[kk][ty * 8 + 4];
            float4 b0 = *(const float4*)&Bs[kk][tx * 4];
            float a[8] = {a0.x, a0.y, a0.z, a0.w, a1.x, a1.y, a1.z, a1.w};
            float b[4] = {b0.x, b0.y, b0.z, b0.w};
            #pragma unroll
            for (int i = 0; i < 8; i++)
                #pragma unroll
                for (int j = 0; j < 4; j++)
                    acc[i][j] += a[i] * b[j];
        }
        __syncthreads();
    }

    // Epilogue: (B,H,T,D) layout. Within this block h is constant (BN==D).
    const int h = n0 >> 6;                 // n0 multiple of 64
    const int dbase = (n0 & 63) + tx * 4;  // = tx*4
    #pragma unroll
    for (int i = 0; i < 8; i++) {
        int m = m0 + ty * 8 + i;
        int b_ = m >> 11;                  // /2048
        int t = m & 2047;
        size_t base = ((size_t)(b_ * HH + h) * TT + t) * DD + dbase;
        float4 v = make_float4(acc[i][0], acc[i][1], acc[i][2], acc[i][3]);
        *(float4*)&Out[base] = v;
        if (dup) *(float4*)&dup[base] = v;
    }
}

// ---------------------------------------------------------------------------
// Flash attention, fp32, causal. One block = 64 queries of one (b,h).
// 256 threads as 16x16; thread owns 4 query rows (ty) x 4 cols (tx).
// ---------------------------------------------------------------------------
#define LD 68                                  // padded tile stride (floats)
#define FLASH_SMEM (4 * 64 * LD * 4)           // Qs,Ks,Vs,Ps = 69632 B

__global__ __launch_bounds__(256) void flash_kernel()
{
    extern __shared__ float sm[];
    float* Qs = sm;                  // [d][r]  (transposed)
    float* Ks = Qs + DD * LD;        // [d][c]  (transposed)
    float* Vs = Ks + DD * LD;        // [c][d]
    float* Ps = Vs + 64 * LD;        // [c][r]  (transposed)

    const int bh = blockIdx.y;                 // 0..31
    const int b_ = bh / HH, h = bh % HH;
    const int q0 = blockIdx.x * 64;
    const int tid = threadIdx.x;
    const int tx = tid & 15, ty = tid >> 4;

    const float* Qg = g_Q + (size_t)bh * TT * DD;
    const float* Kg = g_K + (size_t)bh * TT * DD;
    const float* Vg = g_V + (size_t)bh * TT * DD;

    // Load Q tile (64x64), transpose, pre-scale by 1/sqrt(D)
    #pragma unroll
    for (int i = 0; i < 4; i++) {
        int idx = tid + i * 256;               // 0..1023 float4s
        int r = idx >> 4, dq = idx & 15;
        float4 q4 = *(const float4*)&Qg[(size_t)(q0 + r) * DD + dq * 4];
        int d0 = dq * 4;
        Qs[(d0 + 0) * LD + r] = q4.x * 0.125f;
        Qs[(d0 + 1) * LD + r] = q4.y * 0.125f;
        Qs[(d0 + 2) * LD + r] = q4.z * 0.125f;
        Qs[(d0 + 3) * LD + r] = q4.w * 0.125f;
    }

    float m_i[4], l_i[4], o[4][4];
    #pragma unroll
    for (int j = 0; j < 4; j++) {
        m_i[j] = -INFINITY; l_i[j] = 0.0f;
        #pragma unroll
        for (int jj = 0; jj < 4; jj++) o[j][jj] = 0.0f;
    }

    const int ntiles = blockIdx.x + 1;         // causal: kv tiles 0..qtile
    for (int kt = 0; kt < ntiles; kt++) {
        const int kv0 = kt * 64;
        __syncthreads();                       // guard prev PV reads
        // Load K (transposed) and V tiles
        #pragma unroll
        for (int i = 0; i < 4; i++) {
            int idx = tid + i * 256;
            int c = idx >> 4, dq = idx & 15;
            float4 k4 = *(const float4*)&Kg[(size_t)(kv0 + c) * DD + dq * 4];
            int d0 = dq * 4;
            Ks[(d0 + 0) * LD + c] = k4.x; Ks[(d0 + 1) * LD + c] = k4.y;
            Ks[(d0 + 2) * LD + c] = k4.z; Ks[(d0 + 3) * LD + c] = k4.w;
            *(float4*)&Vs[c * LD + dq * 4] =
                *(const float4*)&Vg[(size_t)(kv0 + c) * DD + dq * 4];
        }
        __syncthreads();

        // S = (Q*scale) K^T : 4x4 per thread
        float s[4][4];
        #pragma unroll
        for (int j = 0; j < 4; j++)
            #pragma unroll
            for (int jj = 0; jj < 4; jj++) s[j][jj] = 0.0f;
        #pragma unroll 8
        for (int d = 0; d < DD; d++) {
            float4 qa = *(const float4*)&Qs[d * LD + ty * 4];
            float4 kb = *(const float4*)&Ks[d * LD + tx * 4];
            float a[4] = {qa.x, qa.y, qa.z, qa.w};
            float b[4] = {kb.x, kb.y, kb.z, kb.w};
            #pragma unroll
            for (int j = 0; j < 4; j++)
                #pragma unroll
                for (int jj = 0; jj < 4; jj++)
                    s[j][jj] += a[j] * b[jj];
        }

        // Causal mask on diagonal tile (kv0 == q0 there)
        if (kt == blockIdx.x) {
            #pragma unroll
            for (int j = 0; j < 4; j++) {
                int r = ty * 4 + j;
                #pragma unroll
                for (int jj = 0; jj < 4; jj++) {
                    int c = tx * 4 + jj;
                    if (c > r) s[j][jj] = -INFINITY;
                }
            }
        }

        // Online softmax (row stats reduced over the 16 tx lanes per row)
        #pragma unroll
        for (int j = 0; j < 4; j++) {
            float mx = fmaxf(fmaxf(s[j][0], s[j][1]), fmaxf(s[j][2], s[j][3]));
            #pragma unroll
            for (int off = 8; off >= 1; off >>= 1)
                mx = fmaxf(mx, __shfl_xor_sync(0xffffffffu, mx, off));
            float mnew = fmaxf(m_i[j], mx);
            float alpha = __expf(m_i[j] - mnew);
            float rsum = 0.0f;
            #pragma unroll
            for (int jj = 0; jj < 4; jj++) {
                float p = __expf(s[j][jj] - mnew);
                s[j][jj] = p;
                rsum += p;
            }
            #pragma unroll
            for (int off = 8; off >= 1; off >>= 1)
                rsum += __shfl_xor_sync(0xffffffffu, rsum, off);
            l_i[j] = l_i[j] * alpha + rsum;
            m_i[j] = mnew;
            #pragma unroll
            for (int jj = 0; jj < 4; jj++) o[j][jj] *= alpha;
        }

        // Stage P transposed: Ps[c][r]
        #pragma unroll
        for (int j = 0; j < 4; j++)
            #pragma unroll
            for (int jj = 0; jj < 4; jj++)
                Ps[(tx * 4 + jj) * LD + ty * 4 + j] = s[j][jj];
        __syncthreads();

        // O += P V : 4x4 per thread
        #pragma unroll 8
        for (int c = 0; c < 64; c++) {
            float4 pa = *(const float4*)&Ps[c * LD + ty * 4];
            float4 vb = *(const float4*)&Vs[c * LD + tx * 4];
            float p[4] = {pa.x, pa.y, pa.z, pa.w};
            float v[4] = {vb.x, vb.y, vb.z, vb.w};
            #pragma unroll
            for (int j = 0; j < 4; j++)
                #pragma unroll
                for (int jj = 0; jj < 4; jj++)
                    o[j][jj] += p[j] * v[jj];
        }
    }

    // Write O/l to g_AO in (B,T,C) layout for the output projection
    #pragma unroll
    for (int j = 0; j < 4; j++) {
        float inv = 1.0f / l_i[j];
        int t = q0 + ty * 4 + j;
        size_t base = ((size_t)b_ * TT + t) * CC + h * DD + tx * 4;
        float4 v = make_float4(o[j][0] * inv, o[j][1] * inv,
                               o[j][2] * inv, o[j][3] * inv);
        *(float4*)&g_AO[base] = v;
    }
}

// ---------------------------------------------------------------------------
// Output projection: out = g_AO @ Wo + bo    (M=4096, N=K=1024)
// ---------------------------------------------------------------------------
__global__ __launch_bounds__(256) void gemm_proj_kernel(
    const float* __restrict__ Wo, const float* __restrict__ bo,
    float* __restrict__ out)
{
    constexpr int BM = 128, BN = 64, BK = 32;
    __shared__ float As[BK][BM + 4];
    __shared__ float Bs[BK][BN + 4];

    const int m0 = blockIdx.x * BM;
    const int n0 = blockIdx.y * BN;
    const int tid = threadIdx.x;
    const int tx = tid & 15, ty = tid >> 4;

    float acc[8][4];
    #pragma unroll
    for (int i = 0; i < 8; i++)
        #pragma unroll
        for (int j = 0; j < 4; j++) acc[i][j] = 0.0f;

    for (int k0 = 0; k0 < CC; k0 += BK) {
        #pragma unroll
        for (int i = 0; i < 4; i++) {
            int idx = tid + i * 256;
            int r = idx >> 3, kq = idx & 7;
            float4 a4 = *(const float4*)&g_AO[(size_t)(m0 + r) * CC + k0 + kq * 4];
            int k4 = kq * 4;
            As[k4 + 0][r] = a4.x; As[k4 + 1][r] = a4.y;
            As[k4 + 2][r] = a4.z; As[k4 + 3][r] = a4.w;
        }
        #pragma unroll
        for (int i = 0; i < 2; i++) {
            int idx = tid + i * 256;
            int kk = idx >> 4, cq = idx & 15;
            *(float4*)&Bs[kk][cq * 4] =
                *(const float4*)&Wo[(size_t)(k0 + kk) * CC + n0 + cq * 4];
        }
        __syncthreads();

        #pragma unroll 8
        for (int kk = 0; kk < BK; kk++) {
            float4 a0 = *(const float4*)&As[kk][ty * 8];
            float4 a1 = *(const float4*)&As[kk][ty * 8 + 4];
            float4 b0 = *(const float4*)&Bs[kk][tx * 4];
            float a[8] = {a0.x, a0.y, a0.z, a0.w, a1.x, a1.y, a1.z, a1.w};
            float b[4] = {b0.x, b0.y, b0.z, b0.w};
            #pragma unroll
            for (int i = 0; i < 8; i++)
                #pragma unroll
                for (int j = 0; j < 4; j++)
                    acc[i][j] += a[i] * b[j];
        }
        __syncthreads();
    }

    float4 bias = *(const float4*)&bo[n0 + tx * 4];
    #pragma unroll
    for (int i = 0; i < 8; i++) {
        int m = m0 + ty * 8 + i;
        float4 v = make_float4(acc[i][0] + bias.x, acc[i][1] + bias.y,
                               acc[i][2] + bias.z, acc[i][3] + bias.w);
        *(float4*)&out[(size_t)m * CC + n0 + tx * 4] = v;
    }
}

// ---------------------------------------------------------------------------
extern "C" void kernel_launch(void* const* d_in, const int* in_sizes, int n_in,
                              void* d_out, int out_size)
{
    const float* x  = (const float*)d_in[0];
    const float* Wq = (const float*)d_in[1];
    const float* Wk = (const float*)d_in[2];
    const float* Wv = (const float*)d_in[3];
    const float* Wo = (const float*)d_in[4];
    const float* bo = (const float*)d_in[5];
    float* out = (float*)d_out;

    // If the harness flattens (out, (k, v)), duplicate K/V into d_out.
    float* kout = nullptr;
    float* vout = nullptr;
    if (out_size >= 3 * NOUT) {
        kout = out + NOUT;
        vout = out + 2 * NOUT;
    }

    // 1. QKV projections (z: 0=Q, 1=K, 2=V)
    gemm_qkv_kernel<<<dim3(MM / 128, CC / 64, 3), 256>>>(x, Wq, Wk, Wv, kout, vout);

    // 2. Causal flash attention
    cudaFuncSetAttribute(flash_kernel,
                         cudaFuncAttributeMaxDynamicSharedMemorySize, FLASH_SMEM);
    flash_kernel<<<dim3(TT / 64, BB * HH), 256, FLASH_SMEM>>>();

    // 3. Output projection + bias
    gemm_proj_kernel<<<dim3(MM / 128, CC / 64), 256>>>(Wo, bo, out);
}

// round 6
// speedup vs baseline: 1.4394x; 1.4394x over previous
#include <cuda_runtime.h>
#include <cuda_bf16.h>
#include <math.h>
#include <stdint.h>

#define BB 2
#define TT 2048
#define CC 1024
#define HH 16
#define DD 64
#define MM (BB*TT)          // 4096
#define NOUT (BB*TT*CC)     // 4194304

// Scratch (allocation-free rule: __device__ globals)
__device__ float g_Q[BB*HH*TT*DD];
__device__ float g_K[BB*HH*TT*DD];
__device__ float g_V[BB*HH*TT*DD];
__device__ __align__(16) __nv_bfloat16 g_Xh[MM*CC];   // split of x
__device__ __align__(16) __nv_bfloat16 g_Xl[MM*CC];
__device__ __align__(16) __nv_bfloat16 g_Wh[4ull*CC*CC];  // W^T hi (n-major, k-contig)
__device__ __align__(16) __nv_bfloat16 g_Wl[4ull*CC*CC];  // W^T lo
__device__ __align__(16) __nv_bfloat16 g_AOh[MM*CC];  // attention out split
__device__ __align__(16) __nv_bfloat16 g_AOl[MM*CC];

// ---------------------------------------------------------------------------
// PTX helpers: mma.sync (HMMA), ldmatrix, cp.async — all valid at compute_103
// ---------------------------------------------------------------------------
__device__ __forceinline__ uint32_t smem_u32(const void* p) {
    uint32_t a;
    asm("{ .reg .u64 t; cvta.to.shared.u64 t, %1; cvt.u32.u64 %0, t; }"
        : "=r"(a) : "l"(p));
    return a;
}

__device__ __forceinline__ void mma16816(float* c, const uint32_t* a, const uint32_t* b) {
    asm volatile(
        "mma.sync.aligned.m16n8k16.row.col.f32.bf16.bf16.f32 "
        "{%0,%1,%2,%3}, {%4,%5,%6,%7}, {%8,%9}, {%0,%1,%2,%3};\n"
        : "+f"(c[0]), "+f"(c[1]), "+f"(c[2]), "+f"(c[3])
        : "r"(a[0]), "r"(a[1]), "r"(a[2]), "r"(a[3]), "r"(b[0]), "r"(b[1]));
}

__device__ __forceinline__ void ldsm4(uint32_t* r, uint32_t addr) {
    asm volatile("ldmatrix.sync.aligned.m8n8.x4.shared.b16 {%0,%1,%2,%3}, [%4];"
                 : "=r"(r[0]), "=r"(r[1]), "=r"(r[2]), "=r"(r[3]) : "r"(addr));
}
__device__ __forceinline__ void ldsm2(uint32_t* r, uint32_t addr) {
    asm volatile("ldmatrix.sync.aligned.m8n8.x2.shared.b16 {%0,%1}, [%2];"
                 : "=r"(r[0]), "=r"(r[1]) : "r"(addr));
}

#define CP_ASYNC16(dst, src) \
    asm volatile("cp.async.cg.shared.global [%0], [%1], 16;" \
                 :: "r"(dst), "l"(src) : "memory")
#define CP_COMMIT() asm volatile("cp.async.commit_group;" ::: "memory")
#define CP_WAIT1()  asm volatile("cp.async.wait_group 1;" ::: "memory")

// fp32 -> bf16 hi/lo split
__device__ __forceinline__ void bsplit(float x, __nv_bfloat16& h, __nv_bfloat16& l) {
    h = __float2bfloat16(x);
    l = __float2bfloat16(x - __bfloat162float(h));
}

// ---------------------------------------------------------------------------
// Prep 1: split x into bf16 hi/lo (same [m][k] layout)
// ---------------------------------------------------------------------------
__global__ __launch_bounds__(256) void split_x_kernel(const float* __restrict__ x)
{
    int i4 = blockIdx.x * 256 + threadIdx.x;          // float4 index
    float4 v = ((const float4*)x)[i4];
    __nv_bfloat16 h[4], l[4];
    bsplit(v.x, h[0], l[0]); bsplit(v.y, h[1], l[1]);
    bsplit(v.z, h[2], l[2]); bsplit(v.w, h[3], l[3]);
    ((__nv_bfloat162*)g_Xh)[i4*2+0] = __nv_bfloat162{h[0], h[1]};
    ((__nv_bfloat162*)g_Xh)[i4*2+1] = __nv_bfloat162{h[2], h[3]};
    ((__nv_bfloat162*)g_Xl)[i4*2+0] = __nv_bfloat162{l[0], l[1]};
    ((__nv_bfloat162*)g_Xl)[i4*2+1] = __nv_bfloat162{l[2], l[3]};
}

// ---------------------------------------------------------------------------
// Prep 2: transpose + split weights: g_Wh/l[z][n][k] = split(W_z[k][n])
// ---------------------------------------------------------------------------
__global__ __launch_bounds__(256) void transpose_split_w_kernel(
    const float* __restrict__ Wq, const float* __restrict__ Wk,
    const float* __restrict__ Wv, const float* __restrict__ Wo)
{
    __shared__ float tile[32][33];
    const int z = blockIdx.z;
    const float* W = (z == 0) ? Wq : (z == 1) ? Wk : (z == 2) ? Wv : Wo;
    __nv_bfloat16* Oh = g_Wh + (size_t)z * CC * CC;
    __nv_bfloat16* Ol = g_Wl + (size_t)z * CC * CC;

    int xcol = blockIdx.x * 32 + threadIdx.x;   // n
    int yrow = blockIdx.y * 32 + threadIdx.y;   // k
    #pragma unroll
    for (int j = 0; j < 32; j += 8)
        tile[threadIdx.y + j][threadIdx.x] = W[(size_t)(yrow + j) * CC + xcol];
    __syncthreads();
    int kk = blockIdx.y * 32 + threadIdx.x;     // k
    int nn = blockIdx.x * 32 + threadIdx.y;     // n
    #pragma unroll
    for (int j = 0; j < 32; j += 8) {
        float v = tile[threadIdx.x][threadIdx.y + j];
        __nv_bfloat16 h, l; bsplit(v, h, l);
        Oh[(size_t)(nn + j) * CC + kk] = h;
        Ol[(size_t)(nn + j) * CC + kk] = l;
    }
}

// ---------------------------------------------------------------------------
// bf16-split HMMA GEMM: 128x128 CTA tile, BK=32, 8 warps (64x32 each),
// cp.async 2-stage pipeline, ldmatrix fragments, 3 MMAs per logical mma.
// mode 0: A=g_Xh/l, B=g_Wh/l[z], out -> g_Q/K/V (+dup k/v)
// mode 1: A=g_AOh/l, B=g_Wh/l[3], out = pout + bias
// ---------------------------------------------------------------------------
#define Bb_M 128
#define Bb_N 128
#define Bb_K 32
#define NCHUNK (CC/Bb_K)              // 32
#define RSTRIDE 80                    // bytes per smem row (40 bf16, 16B-mult, conflict-free)
#define TILE_B (128*RSTRIDE)          // 10240 bytes per matrix tile
#define STAGE_B (4*TILE_B)            // AH,AL,BH,BL = 40960
#define GEMM_SMEM (2*STAGE_B)         // 81920

__global__ __launch_bounds__(256, 1)
void hmma_gemm_kernel(float* __restrict__ kout, float* __restrict__ vout,
                      const float* __restrict__ bo, float* __restrict__ pout,
                      int mode)
{
    extern __shared__ char smem[];
    const uint32_t sb = smem_u32(smem);

    const int tid = threadIdx.x;
    const int wid = tid >> 5;
    const int lane = tid & 31;
    const int m0 = blockIdx.x * Bb_M;
    const int n0 = blockIdx.y * Bb_N;

    const __nv_bfloat16 *pAh, *pAl, *pBh, *pBl;
    float* Out;
    float* dup = nullptr;
    if (mode == 0) {
        pAh = g_Xh; pAl = g_Xl;
        const int z = blockIdx.z;
        pBh = g_Wh + (size_t)z * CC * CC;
        pBl = g_Wl + (size_t)z * CC * CC;
        Out = (z == 0) ? g_Q : (z == 1 ? g_K : g_V);
        if (z == 1) dup = kout;
        else if (z == 2) dup = vout;
    } else {
        pAh = g_AOh; pAl = g_AOl;
        pBh = g_Wh + (size_t)3 * CC * CC;
        pBl = g_Wl + (size_t)3 * CC * CC;
        Out = pout;
    }

    // accumulators: 4 m-tiles x 4 n-tiles of m16n8
    float c[4][4][4];
    #pragma unroll
    for (int i = 0; i < 4; i++)
        #pragma unroll
        for (int j = 0; j < 4; j++)
            #pragma unroll
            for (int q = 0; q < 4; q++) c[i][j][q] = 0.0f;

    const int wm = wid & 1;     // 2 warps over M (64 rows each)
    const int wn = wid >> 1;    // 4 warps over N (32 cols each)

    // ---- stage loader (cp.async) ----
    auto load_stage = [&](int ch, int st) {
        const int k0 = ch * Bb_K;
        #pragma unroll
        for (int i = 0; i < 8; i++) {
            int idx = tid + i * 256;            // 0..2047
            int arr = idx >> 9;                 // 0..3 (const per i)
            int rem = idx & 511;
            int row = rem >> 2, seg = rem & 3;  // seg: 8-elem (16B) chunk
            const __nv_bfloat16* src;
            if (arr == 0)      src = &pAh[(size_t)(m0 + row) * CC + k0 + seg * 8];
            else if (arr == 1) src = &pAl[(size_t)(m0 + row) * CC + k0 + seg * 8];
            else if (arr == 2) src = &pBh[(size_t)(n0 + row) * CC + k0 + seg * 8];
            else               src = &pBl[(size_t)(n0 + row) * CC + k0 + seg * 8];
            uint32_t dst = sb + st * STAGE_B + arr * TILE_B + row * RSTRIDE + seg * 16;
            CP_ASYNC16(dst, src);
        }
        CP_COMMIT();
    };

    load_stage(0, 0);

    // fragment smem address components
    const uint32_t a_row = lane & 15;           // ldmatrix.x4 row
    const uint32_t a_colb = (lane >> 4) * 16;   // byte offset of 8-elem col chunk
    const uint32_t b_row = lane & 7;            // ldmatrix.x2 row (n)
    const uint32_t b_colb = ((lane >> 3) & 1) * 16;

    #pragma unroll 1
    for (int ch = 0; ch < NCHUNK; ch++) {
        if (ch + 1 < NCHUNK) load_stage(ch + 1, (ch + 1) & 1);
        else CP_COMMIT();
        CP_WAIT1();
        __syncthreads();

        const uint32_t s0 = sb + (ch & 1) * STAGE_B;
        #pragma unroll
        for (int ks = 0; ks < 2; ks++) {
            const uint32_t kb = ks * 32;        // byte col offset of k16 step
            uint32_t ah[4][4], al[4][4], bh[4][2], bl[4][2];
            #pragma unroll
            for (int i = 0; i < 4; i++) {
                uint32_t ra = (wm * 64 + i * 16 + a_row) * RSTRIDE + kb + a_colb;
                ldsm4(ah[i], s0 + 0 * TILE_B + ra);
                ldsm4(al[i], s0 + 1 * TILE_B + ra);
            }
            #pragma unroll
            for (int j = 0; j < 4; j++) {
                uint32_t rb = (wn * 32 + j * 8 + b_row) * RSTRIDE + kb + b_colb;
                ldsm2(bh[j], s0 + 2 * TILE_B + rb);
                ldsm2(bl[j], s0 + 3 * TILE_B + rb);
            }
            #pragma unroll
            for (int i = 0; i < 4; i++)
                #pragma unroll
                for (int j = 0; j < 4; j++) {
                    mma16816(c[i][j], ah[i], bh[j]);
                    mma16816(c[i][j], al[i], bh[j]);
                    mma16816(c[i][j], ah[i], bl[j]);
                }
        }
        __syncthreads();
    }

    // ---- epilogue: thread owns (r, 2c) pairs of each 16x8 tile ----
    const int r0 = lane >> 2;
    const int cp2 = (lane & 3) * 2;
    #pragma unroll
    for (int i = 0; i < 4; i++) {
        const int m1 = m0 + wm * 64 + i * 16 + r0;
        #pragma unroll
        for (int j = 0; j < 4; j++) {
            const int n = n0 + wn * 32 + j * 8 + cp2;
            float2 v0 = make_float2(c[i][j][0], c[i][j][1]);
            float2 v1 = make_float2(c[i][j][2], c[i][j][3]);
            if (mode == 0) {
                const int b_ = m1 >> 11, t_ = m1 & 2047;
                const int h = n >> 6, d = n & 63;
                const size_t base = ((size_t)(b_ * HH + h) * TT + t_) * DD + d;
                *(float2*)&Out[base] = v0;
                *(float2*)&Out[base + 8 * DD] = v1;      // row +8
                if (dup) {
                    *(float2*)&dup[base] = v0;
                    *(float2*)&dup[base + 8 * DD] = v1;
                }
            } else {
                float2 bv = *(const float2*)&bo[n];
                v0.x += bv.x; v0.y += bv.y;
                v1.x += bv.x; v1.y += bv.y;
                *(float2*)&Out[(size_t)m1 * CC + n] = v0;
                *(float2*)&Out[(size_t)(m1 + 8) * CC + n] = v1;
            }
        }
    }
}

// ---------------------------------------------------------------------------
// Flash attention, fp32, causal (known-correct). Epilogue now writes bf16
// hi/lo split of the attention output for the HMMA projection.
// ---------------------------------------------------------------------------
#define LD 68
#define FLASH_SMEM (4 * 64 * LD * 4)

__global__ __launch_bounds__(256) void flash_kernel()
{
    extern __shared__ float sm[];
    float* Qs = sm;
    float* Ks = Qs + DD * LD;
    float* Vs = Ks + DD * LD;
    float* Ps = Vs + 64 * LD;

    const int bh = blockIdx.y;
    const int b_ = bh / HH, h = bh % HH;
    const int q0 = blockIdx.x * 64;
    const int tid = threadIdx.x;
    const int tx = tid & 15, ty = tid >> 4;

    const float* Qg = g_Q + (size_t)bh * TT * DD;
    const float* Kg = g_K + (size_t)bh * TT * DD;
    const float* Vg = g_V + (size_t)bh * TT * DD;

    #pragma unroll
    for (int i = 0; i < 4; i++) {
        int idx = tid + i * 256;
        int r = idx >> 4, dq = idx & 15;
        float4 q4 = *(const float4*)&Qg[(size_t)(q0 + r) * DD + dq * 4];
        int d0 = dq * 4;
        Qs[(d0 + 0) * LD + r] = q4.x * 0.125f;
        Qs[(d0 + 1) * LD + r] = q4.y * 0.125f;
        Qs[(d0 + 2) * LD + r] = q4.z * 0.125f;
        Qs[(d0 + 3) * LD + r] = q4.w * 0.125f;
    }

    float m_i[4], l_i[4], o[4][4];
    #pragma unroll
    for (int j = 0; j < 4; j++) {
        m_i[j] = -INFINITY; l_i[j] = 0.0f;
        #pragma unroll
        for (int jj = 0; jj < 4; jj++) o[j][jj] = 0.0f;
    }

    const int ntiles = blockIdx.x + 1;
    for (int kt = 0; kt < ntiles; kt++) {
        const int kv0 = kt * 64;
        __syncthreads();
        #pragma unroll
        for (int i = 0; i < 4; i++) {
            int idx = tid + i * 256;
            int ccol = idx >> 4, dq = idx & 15;
            float4 k4 = *(const float4*)&Kg[(size_t)(kv0 + ccol) * DD + dq * 4];
            int d0 = dq * 4;
            Ks[(d0 + 0) * LD + ccol] = k4.x; Ks[(d0 + 1) * LD + ccol] = k4.y;
            Ks[(d0 + 2) * LD + ccol] = k4.z; Ks[(d0 + 3) * LD + ccol] = k4.w;
            *(float4*)&Vs[ccol * LD + dq * 4] =
                *(const float4*)&Vg[(size_t)(kv0 + ccol) * DD + dq * 4];
        }
        __syncthreads();

        float s[4][4];
        #pragma unroll
        for (int j = 0; j < 4; j++)
            #pragma unroll
            for (int jj = 0; jj < 4; jj++) s[j][jj] = 0.0f;
        #pragma unroll 8
        for (int d = 0; d < DD; d++) {
            float4 qa = *(const float4*)&Qs[d * LD + ty * 4];
            float4 kb = *(const float4*)&Ks[d * LD + tx * 4];
            float a[4] = {qa.x, qa.y, qa.z, qa.w};
            float b[4] = {kb.x, kb.y, kb.z, kb.w};
            #pragma unroll
            for (int j = 0; j < 4; j++)
                #pragma unroll
                for (int jj = 0; jj < 4; jj++)
                    s[j][jj] += a[j] * b[jj];
        }

        if (kt == blockIdx.x) {
            #pragma unroll
            for (int j = 0; j < 4; j++) {
                int r = ty * 4 + j;
                #pragma unroll
                for (int jj = 0; jj < 4; jj++) {
                    int ccol = tx * 4 + jj;
                    if (ccol > r) s[j][jj] = -INFINITY;
                }
            }
        }

        #pragma unroll
        for (int j = 0; j < 4; j++) {
            float mx = fmaxf(fmaxf(s[j][0], s[j][1]), fmaxf(s[j][2], s[j][3]));
            #pragma unroll
            for (int off = 8; off >= 1; off >>= 1)
                mx = fmaxf(mx, __shfl_xor_sync(0xffffffffu, mx, off));
            float mnew = fmaxf(m_i[j], mx);
            float alpha = __expf(m_i[j] - mnew);
            float rsum = 0.0f;
            #pragma unroll
            for (int jj = 0; jj < 4; jj++) {
                float p = __expf(s[j][jj] - mnew);
                s[j][jj] = p;
                rsum += p;
            }
            #pragma unroll
            for (int off = 8; off >= 1; off >>= 1)
                rsum += __shfl_xor_sync(0xffffffffu, rsum, off);
            l_i[j] = l_i[j] * alpha + rsum;
            m_i[j] = mnew;
            #pragma unroll
            for (int jj = 0; jj < 4; jj++) o[j][jj] *= alpha;
        }

        #pragma unroll
        for (int j = 0; j < 4; j++)
            #pragma unroll
            for (int jj = 0; jj < 4; jj++)
                Ps[(tx * 4 + jj) * LD + ty * 4 + j] = s[j][jj];
        __syncthreads();

        #pragma unroll 8
        for (int ccol = 0; ccol < 64; ccol++) {
            float4 pa = *(const float4*)&Ps[ccol * LD + ty * 4];
            float4 vb = *(const float4*)&Vs[ccol * LD + tx * 4];
            float p[4] = {pa.x, pa.y, pa.z, pa.w};
            float v[4] = {vb.x, vb.y, vb.z, vb.w};
            #pragma unroll
            for (int j = 0; j < 4; j++)
                #pragma unroll
                for (int jj = 0; jj < 4; jj++)
                    o[j][jj] += p[j] * v[jj];
        }
    }

    // Epilogue: split attention output to bf16 hi/lo in (B,T,C) layout
    #pragma unroll
    for (int j = 0; j < 4; j++) {
        float inv = 1.0f / l_i[j];
        int t = q0 + ty * 4 + j;
        size_t base = ((size_t)b_ * TT + t) * CC + h * DD + tx * 4;
        __nv_bfloat16 hh[4], ll[4];
        #pragma unroll
        for (int jj = 0; jj < 4; jj++) bsplit(o[j][jj] * inv, hh[jj], ll[jj]);
        *(__nv_bfloat162*)&g_AOh[base]     = __nv_bfloat162{hh[0], hh[1]};
        *(__nv_bfloat162*)&g_AOh[base + 2] = __nv_bfloat162{hh[2], hh[3]};
        *(__nv_bfloat162*)&g_AOl[base]     = __nv_bfloat162{ll[0], ll[1]};
        *(__nv_bfloat162*)&g_AOl[base + 2] = __nv_bfloat162{ll[2], ll[3]};
    }
}

// ---------------------------------------------------------------------------
extern "C" void kernel_launch(void* const* d_in, const int* in_sizes, int n_in,
                              void* d_out, int out_size)
{
    const float* x  = (const float*)d_in[0];
    const float* Wq = (const float*)d_in[1];
    const float* Wk = (const float*)d_in[2];
    const float* Wv = (const float*)d_in[3];
    const float* Wo = (const float*)d_in[4];
    const float* bo = (const float*)d_in[5];
    float* out = (float*)d_out;

    float* kout = nullptr;
    float* vout = nullptr;
    if (out_size >= 3 * NOUT) {
        kout = out + NOUT;
        vout = out + 2 * NOUT;
    }

    // 0. Prep: split x; transpose+split weights
    split_x_kernel<<<MM * CC / 1024, 256>>>(x);
    transpose_split_w_kernel<<<dim3(32, 32, 4), dim3(32, 8)>>>(Wq, Wk, Wv, Wo);

    // 1. QKV projections (HMMA bf16 split)
    cudaFuncSetAttribute(hmma_gemm_kernel,
                         cudaFuncAttributeMaxDynamicSharedMemorySize, GEMM_SMEM);
    hmma_gemm_kernel<<<dim3(MM / Bb_M, CC / Bb_N, 3), 256, GEMM_SMEM>>>(
        kout, vout, nullptr, nullptr, 0);

    // 2. Causal flash attention (fp32)
    cudaFuncSetAttribute(flash_kernel,
                         cudaFuncAttributeMaxDynamicSharedMemorySize, FLASH_SMEM);
    flash_kernel<<<dim3(TT / 64, BB * HH), 256, FLASH_SMEM>>>();

    // 3. Output projection + bias (HMMA bf16 split)
    hmma_gemm_kernel<<<dim3(MM / Bb_M, CC / Bb_N, 1), 256, GEMM_SMEM>>>(
        nullptr, nullptr, bo, out, 1);
}